// round 1
// baseline (speedup 1.0000x reference)
#include <cuda_runtime.h>
#include <cstdint>

// Problem constants (fixed by the reference):
//   NUM_BLOCKS=8192, BLOCK_SIZE=16, NUM_HEADS=8, HEAD_SIZE=128
//   NUM_TOKENS=65536, NUM_SLOTS = 8192*16 = 131072
//   per-slot payload = 8*128 fp32 = 1024 floats = 4096 bytes = 256 float4
#define NUM_SLOTS   131072
#define NUM_TOKENS  65536
#define FLOATS_PER_SLOT 1024
#define VEC4_PER_SLOT   256

// Scratch: inverse slot map. inv_map[slot] = token index writing that slot, or -1.
__device__ int g_inv_map[NUM_SLOTS];

__global__ void init_inv_map_kernel() {
    int i = blockIdx.x * blockDim.x + threadIdx.x;
    if (i < NUM_SLOTS) g_inv_map[i] = -1;
}

__global__ void scatter_inv_map_kernel(const int* __restrict__ slot_mapping) {
    int i = blockIdx.x * blockDim.x + threadIdx.x;
    if (i < NUM_TOKENS) g_inv_map[slot_mapping[i]] = i;
}

// One block per slot; 256 threads each move one float4 (16 B) of the 4 KiB slot.
// Source is either the gathered token row (to_cache) or the original cache row.
__global__ void __launch_bounds__(256) merge_write_kernel(
    const float4* __restrict__ to_cache,
    const float4* __restrict__ kv_cache,
    float4* __restrict__ out)
{
    const unsigned slot = blockIdx.x;
    const int src = g_inv_map[slot];  // uniform per block, broadcast load
    const size_t dst_base = (size_t)slot * VEC4_PER_SLOT;
    const float4* __restrict__ srcp =
        (src >= 0) ? (to_cache + (size_t)src * VEC4_PER_SLOT)
                   : (kv_cache + dst_base);
    out[dst_base + threadIdx.x] = srcp[threadIdx.x];
}

extern "C" void kernel_launch(void* const* d_in, const int* in_sizes, int n_in,
                              void* d_out, int out_size)
{
    const float4* to_cache     = (const float4*)d_in[0];  // [65536, 8, 128] f32
    const float4* kv_cache     = (const float4*)d_in[1];  // [8192, 16, 8, 128] f32
    const int*    slot_mapping = (const int*)d_in[2];     // [65536] i32
    float4*       out          = (float4*)d_out;          // full updated kv_cache

    init_inv_map_kernel<<<(NUM_SLOTS + 255) / 256, 256>>>();
    scatter_inv_map_kernel<<<(NUM_TOKENS + 255) / 256, 256>>>(slot_mapping);
    merge_write_kernel<<<NUM_SLOTS, 256>>>(to_cache, kv_cache, out);
}

// round 2
// speedup vs baseline: 1.2285x; 1.2285x over previous
#include <cuda_runtime.h>
#include <cstdint>

// Problem constants (fixed by the reference):
//   NUM_BLOCKS=8192, BLOCK_SIZE=16, NUM_HEADS=8, HEAD_SIZE=128
//   NUM_TOKENS=65536, NUM_SLOTS = 8192*16 = 131072
//   per-slot payload = 8*128 fp32 = 1024 floats = 4096 bytes = 256 float4
#define NUM_SLOTS       131072
#define NUM_TOKENS      65536
#define VEC4_PER_SLOT   256
#define SLOTS_PER_BLOCK 4

// Scratch: inverse slot map. inv_map[slot] = token index writing that slot, or -1.
__device__ int g_inv_map[NUM_SLOTS];

__global__ void scatter_inv_map_kernel(const int* __restrict__ slot_mapping) {
    int i = blockIdx.x * blockDim.x + threadIdx.x;
    if (i < NUM_TOKENS) g_inv_map[slot_mapping[i]] = i;
}

// One block per 4 consecutive slots; 256 threads each move float4 #t of each
// of the 4 slots. 4 independent 16B load chains per thread (MLP=4), all
// fully coalesced. Streaming hints: data has zero reuse.
__global__ void __launch_bounds__(256) merge_write_kernel(
    const float4* __restrict__ to_cache,
    const float4* __restrict__ kv_cache,
    float4* __restrict__ out)
{
    const unsigned slot_base = blockIdx.x * SLOTS_PER_BLOCK;
    const unsigned t = threadIdx.x;

    // Per-slot source resolution (4 ints, same 16B cacheline, broadcast).
    const float4* srcp[SLOTS_PER_BLOCK];
#pragma unroll
    for (int s = 0; s < SLOTS_PER_BLOCK; s++) {
        const unsigned slot = slot_base + s;
        const int src = g_inv_map[slot];
        srcp[s] = (src >= 0) ? (to_cache + (size_t)src * VEC4_PER_SLOT)
                             : (kv_cache + (size_t)slot * VEC4_PER_SLOT);
    }

    // Front-batch the 4 independent loads, then the 4 stores.
    float4 v[SLOTS_PER_BLOCK];
#pragma unroll
    for (int s = 0; s < SLOTS_PER_BLOCK; s++)
        v[s] = __ldcs(srcp[s] + t);
#pragma unroll
    for (int s = 0; s < SLOTS_PER_BLOCK; s++)
        __stcs(out + (size_t)(slot_base + s) * VEC4_PER_SLOT + t, v[s]);
}

extern "C" void kernel_launch(void* const* d_in, const int* in_sizes, int n_in,
                              void* d_out, int out_size)
{
    const float4* to_cache     = (const float4*)d_in[0];  // [65536, 8, 128] f32
    const float4* kv_cache     = (const float4*)d_in[1];  // [8192, 16, 8, 128] f32
    const int*    slot_mapping = (const int*)d_in[2];     // [65536] i32
    float4*       out          = (float4*)d_out;          // full updated kv_cache

    // Init inv_map to -1 via memset node (0xFF bytes == -1 int).
    void* inv_map_ptr = nullptr;
    cudaGetSymbolAddress(&inv_map_ptr, g_inv_map);
    cudaMemsetAsync(inv_map_ptr, 0xFF, NUM_SLOTS * sizeof(int));

    scatter_inv_map_kernel<<<(NUM_TOKENS + 255) / 256, 256>>>(slot_mapping);
    merge_write_kernel<<<NUM_SLOTS / SLOTS_PER_BLOCK, 256>>>(to_cache, kv_cache, out);
}